// round 16
// baseline (speedup 1.0000x reference)
#include <cuda_runtime.h>
#include <cuda_bf16.h>
#include <mma.h>
#include <math.h>
#include <stdint.h>

using namespace nvcuda;

// Problem constants
#define BB 256
#define TT 30
#define ML 31
#define VV 10000
#define HH 512
#define G4 2048            // 4*H
#define NROWS 7680         // TT*BB
#define BKB 64             // K-chunk (bf16 elems)
#define LDAB 72            // shared lda in bf16 elems (64 + 8 pad) -> 144B rows
#define LDC 132            // shared C ld (floats, 128 + 4 pad)
#define LDC3 36            // shared C ld for 32-wide tiles
#define BUFB (128 * LDAB)  // bf16 elems per A stage buffer (9216)
#define NSTG 3             // pipeline stages
#define DSMEM_BYTES (NSTG * 2 * BUFB * 2)          // 110592 B (k_proj GEMMs)
// fused kernel: steps role and out1 role share 82944 B smem
#define ACH2 (64 * LDAB)   // 4608 bf16 (64-row stage)
#define BCH3 (32 * LDAB)   // 2304 bf16 (B chunk, 32 gate rows)
#define BCHO (128 * LDAB)  // 9216 bf16 (out1 B stage, 128 rows)
#define NCHUNK 8
#define FS_GP 0
#define FS_XP 2048
#define FS_CC 4096
#define DSMEM_FUSED ((3 * ACH2 + NCHUNK * BCH3) * 2 + (2048 + 2048 + 512) * 4)  // 82944 B
#define GRPBLK 64          // blocks per barrier group (steps role)
#define NBG 4
#define BROWS 64
#define NSTEPBLK 256       // steps-role blocks (must fit wave 1: 256 < 296)
#define MT_MAX 120         // max out1 m-tiles (ceil(7680/64))
#define NT_OUT1 79         // out1 n-tiles

typedef __nv_bfloat16 bf16;

// ---------------- device scratch ----------------
__device__ int   g_order[BB];
__device__ int   g_declen[BB];
__device__ int   g_cnt[TT];
__device__ int   g_rowmap[NROWS];
__device__ int   g_ntot;
__device__ float g_gp[BB * G4];
__device__ float g_xp[(size_t)NROWS * G4];
__device__ float g_rowsum[NROWS];
__device__ int   g_barcnt2[NBG];
__device__ int   g_barflag2[NBG];
__device__ bf16  g_Wih_bf[G4 * 1024];
__device__ bf16  g_Whh_bf[G4 * HH];
__device__ bf16  g_Wout_bf[VV * HH];
__device__ bf16  g_emb_bf[VV * HH];
__device__ bf16  g_gimg_bf[BB * HH];
__device__ bf16  g_hbuf_bf[2][BB * HH];
__device__ bf16  g_hall_bf[(size_t)NROWS * HH];

typedef wmma::fragment<wmma::matrix_a, 16, 16, 16, bf16, wmma::row_major> FragA;
typedef wmma::fragment<wmma::matrix_b, 16, 16, 16, bf16, wmma::col_major> FragB;
typedef wmma::fragment<wmma::accumulator, 16, 16, 16, float> FragC;

__device__ __forceinline__ void cp16(void* s, const void* g) {
    unsigned d = (unsigned)__cvta_generic_to_shared(s);
    asm volatile("cp.async.cg.shared.global [%0], [%1], 16;" :: "r"(d), "l"(g));
}

// ---- 3-stage pipelined bf16 GEMM (256 threads; k_proj only) ----
__device__ __forceinline__ void gemm_bf16(const bf16* arow, const bf16* brow,
                                          bf16* As, bf16* Bs,
                                          FragC (&c)[2][4], int tid) {
    int wp = tid >> 5, wm = wp & 3, wn = wp >> 2;
    int srow = tid >> 1, sc = (tid & 1) * 32;
    bf16* asd = As + srow * LDAB + sc;
    bf16* bsd = Bs + srow * LDAB + sc;
    const bf16* ag = arow + sc;
    const bf16* bg = brow + sc;
    #pragma unroll
    for (int q = 0; q < 32; q += 8) { cp16(asd + q, ag + q); cp16(bsd + q, bg + q); }
    asm volatile("cp.async.commit_group;");
    #pragma unroll
    for (int q = 0; q < 32; q += 8) {
        cp16(asd + BUFB + q, ag + BKB + q);
        cp16(bsd + BUFB + q, bg + BKB + q);
    }
    asm volatile("cp.async.commit_group;");
    int buf = 0;
    #pragma unroll 1
    for (int k0 = 0; k0 < HH; k0 += BKB) {
        if (k0 + BKB < HH) asm volatile("cp.async.wait_group 1;" ::: "memory");
        else               asm volatile("cp.async.wait_group 0;" ::: "memory");
        __syncthreads();
        if (k0 + 2 * BKB < HH) {
            int nb = buf + 2; if (nb >= NSTG) nb -= NSTG;
            #pragma unroll
            for (int q = 0; q < 32; q += 8) {
                cp16(asd + nb * BUFB + q, ag + k0 + 2 * BKB + q);
                cp16(bsd + nb * BUFB + q, bg + k0 + 2 * BKB + q);
            }
            asm volatile("cp.async.commit_group;");
        }
        bf16* Ab = As + buf * BUFB;
        bf16* Bb = Bs + buf * BUFB;
        #pragma unroll
        for (int kk = 0; kk < BKB; kk += 16) {
            FragA a0, a1; FragB bf[4];
            wmma::load_matrix_sync(a0, &Ab[(wm * 32)      * LDAB + kk], LDAB);
            wmma::load_matrix_sync(a1, &Ab[(wm * 32 + 16) * LDAB + kk], LDAB);
            #pragma unroll
            for (int j = 0; j < 4; j++)
                wmma::load_matrix_sync(bf[j], &Bb[(wn * 64 + j * 16) * LDAB + kk], LDAB);
            #pragma unroll
            for (int j = 0; j < 4; j++) {
                wmma::mma_sync(c[0][j], a0, bf[j], c[0][j]);
                wmma::mma_sync(c[1][j], a1, bf[j], c[1][j]);
            }
        }
        buf = (buf == NSTG - 1) ? 0 : buf + 1;
    }
    __syncthreads();
}

#define FRAG_INIT(c)                                     \
    _Pragma("unroll")                                    \
    for (int i = 0; i < 2; i++)                          \
        _Pragma("unroll")                                \
        for (int j = 0; j < 4; j++) wmma::fill_fragment(c[i][j], 0.f);

#define FRAG_TO_CS(c, Cs, wm, wn)                                                  \
    _Pragma("unroll")                                                              \
    for (int i = 0; i < 2; i++)                                                    \
        _Pragma("unroll")                                                          \
        for (int j = 0; j < 4; j++)                                                \
            wmma::store_matrix_sync(&Cs[(wm * 32 + i * 16) * LDC + wn * 64 + j * 16], \
                                    c[i][j], LDC, wmma::mem_row_major);

// ---------------- fp32 -> bf16 conversion + state init (merged) ----------------
#define N_WIH (G4 * 1024)
#define N_WHH (G4 * HH)
#define N_WOUT (VV * HH)
#define N_EMB (VV * HH)
#define N_GIMG (BB * HH)
#define N_CVT2 ((N_WIH + N_WHH + N_WOUT + N_EMB + N_GIMG) / 2)

__global__ __launch_bounds__(256) void k_cvt(const float* __restrict__ Wih,
                                             const float* __restrict__ Whh,
                                             const float* __restrict__ Wout,
                                             const float* __restrict__ emb,
                                             const float* __restrict__ gimg) {
    long long i2 = (long long)blockIdx.x * 256 + threadIdx.x;
    if (i2 < BB * HH) {
        g_hbuf_bf[0][i2] = __float2bfloat16(0.f);
        g_hbuf_bf[1][i2] = __float2bfloat16(0.f);
    }
    if (i2 < NROWS) g_rowsum[i2] = 0.f;
    if (i2 < NBG) { g_barcnt2[i2] = 0; g_barflag2[i2] = 0; }
    if (i2 >= N_CVT2) return;
    long long i = i2 * 2;
    const float* src; bf16* dst; long long off;
    if (i < N_WIH)                       { src = Wih;  dst = g_Wih_bf;  off = i; }
    else if (i < (long long)N_WIH + N_WHH) { src = Whh;  dst = g_Whh_bf;  off = i - N_WIH; }
    else if (i < (long long)N_WIH + N_WHH + N_WOUT)
                                         { src = Wout; dst = g_Wout_bf; off = i - N_WIH - N_WHH; }
    else if (i < (long long)N_WIH + N_WHH + N_WOUT + N_EMB)
                                         { src = emb;  dst = g_emb_bf;  off = i - N_WIH - N_WHH - N_WOUT; }
    else                                 { src = gimg; dst = g_gimg_bf; off = i - N_WIH - N_WHH - N_WOUT - N_EMB; }
    float2 v = *(const float2*)(src + off);
    __nv_bfloat162 o = __floats2bfloat162_rn(v.x, v.y);
    *(__nv_bfloat162*)(dst + off) = o;
}

// ---------------- prep: sort + targets + packed row map ----------------
__global__ void k_prep(const int* __restrict__ w, const int* __restrict__ cap,
                       float* __restrict__ out, long long out_size) {
    __shared__ int lens[BB];
    __shared__ int off[TT + 1];
    int i = threadIdx.x;
    lens[i] = cap[i];
    __syncthreads();
    int li = lens[i];
    int rank = 0;
    #pragma unroll 8
    for (int j = 0; j < BB; j++) {
        int lj = lens[j];
        rank += (lj > li) || (lj == li && j < i);
    }
    g_order[rank]  = i;
    g_declen[rank] = li - 1;
    __syncthreads();

    if (i < TT) {
        int c = 0;
        for (int j = 0; j < BB; j++) c += (g_declen[j] > i);
        g_cnt[i] = c;
    }
    __syncthreads();
    if (i == 0) {
        int s = 0;
        for (int t = 0; t < TT; t++) { off[t] = s; s += g_cnt[t]; }
        off[TT] = s;
        g_ntot = s;
    }
    __syncthreads();
    for (int t = 0; t < TT; t++) {
        int c = g_cnt[t];
        for (int b = i; b < c; b += 256) g_rowmap[off[t] + b] = t * 256 + b;
    }
    for (int r = off[TT] + i; r < NROWS; r += 256) g_rowmap[r] = 0;

    long long PRED = (long long)BB * ML * VV;
    if (out_size >= PRED + (long long)BB * TT + BB) {
        int src = g_order[i];
        for (int k = 0; k < TT; k++)
            out[PRED + (long long)i * TT + k] = (float)w[src * ML + k + 1];
        out[PRED + (long long)BB * TT + i] = (float)g_declen[i];
    }
}

// ---- union projection kernel (unchanged from R15) ----
__global__ __launch_bounds__(256, 2) void k_proj(const int* __restrict__ w,
                                                 const float* __restrict__ bih,
                                                 const float* __restrict__ bhh) {
    extern __shared__ bf16 dsm[];
    int tid = threadIdx.x;
    int srow = tid >> 1;
    int wp = tid >> 5, wm = wp & 3, wn = wp >> 2;
    int n0 = blockIdx.x * 128;

    if (blockIdx.y >= 60) {
        int m0 = (blockIdx.y - 60) * 128;
        const bf16* arow = g_gimg_bf + (size_t)g_order[m0 + srow] * HH;
        const bf16* brow = g_Wih_bf + (size_t)(n0 + srow) * 1024;
        FragC c[2][4];
        FRAG_INIT(c);
        gemm_bf16(arow, brow, dsm, dsm + NSTG * BUFB, c, tid);
        float* Cs = (float*)dsm;
        FRAG_TO_CS(c, Cs, wm, wn);
        __syncthreads();
        int row = tid >> 1, cb = (tid & 1) * 64;
        int b = m0 + row;
        #pragma unroll
        for (int q = 0; q < 16; q++) {
            int n = n0 + cb + q * 4;
            float4 cv = *(const float4*)&Cs[row * LDC + cb + q * 4];
            float4 b1 = *(const float4*)(bih + n);
            float4 b2 = *(const float4*)(bhh + n);
            float4 v;
            v.x = cv.x + b1.x + b2.x;
            v.y = cv.y + b1.y + b2.y;
            v.z = cv.z + b1.z + b2.z;
            v.w = cv.w + b1.w + b2.w;
            *(float4*)(g_gp + (size_t)b * G4 + n) = v;
        }
        return;
    }

    int m0 = blockIdx.y * 128;
    int ntot = g_ntot;
    if (m0 >= ntot) return;
    int tb = g_rowmap[m0 + srow];
    int t_r = tb >> 8, b_r = tb & 255;
    int word = w[g_order[b_r] * ML + t_r];
    const bf16* arow = g_emb_bf + (size_t)word * HH;
    const bf16* brow = g_Wih_bf + (size_t)(n0 + srow) * 1024 + 512;
    FragC c[2][4];
    FRAG_INIT(c);
    gemm_bf16(arow, brow, dsm, dsm + NSTG * BUFB, c, tid);
    float* Cs = (float*)dsm;
    FRAG_TO_CS(c, Cs, wm, wn);
    __syncthreads();
    int row = tid >> 1, cb = (tid & 1) * 64;
    int r = m0 + row;
    if (r < ntot) {
        int tb2 = g_rowmap[r];
        size_t xb = (size_t)tb2 * G4;
        #pragma unroll
        for (int q = 0; q < 16; q++) {
            int n = n0 + cb + q * 4;
            *(float4*)(g_xp + xb + n) = *(const float4*)&Cs[row * LDC + cb + q * 4];
        }
    }
}

// ================== fused persistent kernel ==================
// blocks [0, 256): recurrence (4 b-groups x 64 h-tiles), R15 design.
// blocks [256, ...): out1 tiles (64 rows x 128 vocab cols), gated on progress
// flags; m-tile-major order so earliest-t tiles schedule first.
__global__ __launch_bounds__(128, 2) void k_fused(const float* __restrict__ bout,
                                                  float* __restrict__ out) {
    extern __shared__ bf16 dsm[];
    int tid = threadIdx.x;
    int bid = blockIdx.x;

    if (bid < NSTEPBLK) {
        // ---------------- steps role ----------------
        bf16* Af = dsm;                          // 3 x ACH2
        bf16* Br = dsm + 3 * ACH2;               // 8 x BCH3
        float* fsm = (float*)(dsm + 3 * ACH2 + NCHUNK * BCH3);
        float* gpS = fsm + FS_GP;
        float* xpS = fsm + FS_XP;
        float* ccS = fsm + FS_CC;
        float* Cs = (float*)dsm;
        int grp = bid >> 6;                      // 0..3
        int h0 = (bid & 63) * 8;
        int b0 = grp * BROWS;
        int wp = tid >> 5, wm = wp & 1, wn = wp >> 1;
        int srowA = tid >> 1, scA = (tid & 1) * 32;
        int rowX = tid >> 1, halfX = tid & 1;

        {
            int row4 = tid >> 2, c16 = (tid & 3) * 16;
            int gate = row4 >> 3, hh_s = row4 & 7;
            const bf16* bg = g_Whh_bf + (size_t)(gate * 512 + h0 + hh_s) * HH;
            #pragma unroll
            for (int ch = 0; ch < NCHUNK; ch++) {
                bf16* d = Br + ch * BCH3 + row4 * LDAB + c16;
                const bf16* s = bg + ch * BKB + c16;
                cp16(d, s); cp16(d + 8, s + 8);
            }
            #pragma unroll
            for (int g2 = 0; g2 < 2; g2++) {
                int gate2 = halfX * 2 + g2;
                const float* s = g_gp + (size_t)(b0 + rowX) * G4 + gate2 * 512 + h0;
                float* d = gpS + rowX * 32 + gate2 * 8;
                cp16(d, s); cp16(d + 4, s + 4);
            }
            asm volatile("cp.async.commit_group;");
            asm volatile("cp.async.wait_group 0;" ::: "memory");
            #pragma unroll
            for (int i = 0; i < 4; i++) ccS[tid * 4 + i] = 0.f;
            __syncthreads();
        }

        for (int t = 0; t < TT; t++) {
            int cnt = g_cnt[t];
            if (cnt <= b0) break;
            FragC c[2];
            wmma::fill_fragment(c[0], 0.f);
            wmma::fill_fragment(c[1], 0.f);
            const bf16* ag = g_hbuf_bf[t & 1] + (size_t)(b0 + srowA) * HH + scA;
            bf16* asd = Af + srowA * LDAB + scA;
            #pragma unroll
            for (int q = 0; q < 32; q += 8) cp16(asd + q, ag + q);
            asm volatile("cp.async.commit_group;");
            #pragma unroll
            for (int q = 0; q < 32; q += 8) cp16(asd + ACH2 + q, ag + BKB + q);
            asm volatile("cp.async.commit_group;");

            #pragma unroll 1
            for (int ch = 0; ch < NCHUNK; ch++) {
                if (ch < NCHUNK - 1) asm volatile("cp.async.wait_group 1;" ::: "memory");
                else                 asm volatile("cp.async.wait_group 0;" ::: "memory");
                __syncthreads();
                if (ch < NCHUNK - 2) {
                    int dch = ch + 2;
                    int dbuf = dch; while (dbuf >= 3) dbuf -= 3;
                    const bf16* s = ag + dch * BKB;
                    bf16* d = asd + dbuf * ACH2;
                    #pragma unroll
                    for (int q = 0; q < 32; q += 8) cp16(d + q, s + q);
                    if (ch == 0) {
                        #pragma unroll
                        for (int g2 = 0; g2 < 2; g2++) {
                            int gate2 = halfX * 2 + g2;
                            const float* xs = g_xp + (size_t)(t * BB + b0 + rowX) * G4
                                              + gate2 * 512 + h0;
                            float* xd = xpS + rowX * 32 + gate2 * 8;
                            cp16(xd, xs); cp16(xd + 4, xs + 4);
                        }
                    }
                    asm volatile("cp.async.commit_group;");
                }
                int cbuf = ch; while (cbuf >= 3) cbuf -= 3;
                bf16* Ab = Af + cbuf * ACH2;
                bf16* Bb = Br + ch * BCH3;
                #pragma unroll
                for (int kk = 0; kk < BKB; kk += 16) {
                    FragA a0, a1; FragB bf0;
                    wmma::load_matrix_sync(a0, &Ab[(wm * 32)      * LDAB + kk], LDAB);
                    wmma::load_matrix_sync(a1, &Ab[(wm * 32 + 16) * LDAB + kk], LDAB);
                    wmma::load_matrix_sync(bf0, &Bb[(wn * 16) * LDAB + kk], LDAB);
                    wmma::mma_sync(c[0], a0, bf0, c[0]);
                    wmma::mma_sync(c[1], a1, bf0, c[1]);
                }
            }
            __syncthreads();
            wmma::store_matrix_sync(&Cs[(wm * 32)      * LDC3 + wn * 16], c[0], LDC3,
                                    wmma::mem_row_major);
            wmma::store_matrix_sync(&Cs[(wm * 32 + 16) * LDC3 + wn * 16], c[1], LDC3,
                                    wmma::mem_row_major);
            __syncthreads();
            #pragma unroll
            for (int it = 0; it < 4; it++) {
                int p = it * 128 + tid;
                int row = p >> 3;
                int hh = p & 7;
                int b = b0 + row;
                if (b >= cnt) continue;
                int r32 = row * 32 + hh;
                float iv = Cs[row * LDC3 + 0  + hh] + xpS[r32]      + gpS[r32];
                float fv = Cs[row * LDC3 + 8  + hh] + xpS[r32 + 8]  + gpS[r32 + 8];
                float gv = Cs[row * LDC3 + 16 + hh] + xpS[r32 + 16] + gpS[r32 + 16];
                float ov = Cs[row * LDC3 + 24 + hh] + xpS[r32 + 24] + gpS[r32 + 24];
                iv = 1.f / (1.f + __expf(-iv));
                fv = 1.f / (1.f + __expf(-fv));
                ov = 1.f / (1.f + __expf(-ov));
                gv = tanhf(gv);
                int ci = row * 8 + hh;
                float cn = fv * ccS[ci] + iv * gv;
                float hn = ov * tanhf(cn);
                ccS[ci] = cn;
                bf16 hb = __float2bfloat16(hn);
                int hidx = b * HH + h0 + hh;
                g_hbuf_bf[(t + 1) & 1][hidx] = hb;
                g_hall_bf[(size_t)(t * BB + b) * HH + h0 + hh] = hb;
            }
            __syncthreads();
            __threadfence();
            if (tid == 0) {
                int v = atomicAdd(&g_barcnt2[grp], 1);
                if (v == GRPBLK - 1) {
                    atomicExch(&g_barcnt2[grp], 0);
                    __threadfence();
                    atomicExch(&g_barflag2[grp], t + 1);
                } else {
                    while (atomicAdd(&g_barflag2[grp], 0) < t + 1) { __nanosleep(32); }
                    __threadfence();
                }
            }
            __syncthreads();
        }
        return;
    }

    // ---------------- out1 role: 64 rows x 128 cols x K=512 ----------------
    int idx = bid - NSTEPBLK;
    int mt = idx / NT_OUT1, nt = idx - mt * NT_OUT1;
    int m0 = mt * 64;
    int ntot = g_ntot;
    if (m0 >= ntot) return;
    int n0 = nt * 128;

    bf16* As = dsm;                  // 3 x ACH2 (64-row stages)
    bf16* Bs = dsm + 3 * ACH2;       // 3 x BCHO (128-row stages)
    float* Cs = (float*)dsm;         // 64 x LDC after compute
    __shared__ int needf[NBG];
    __shared__ int rowsS[64];

    if (tid < NBG) needf[tid] = 0;
    __syncthreads();
    if (tid < 64) {
        int r = m0 + tid;
        int tb = (r < ntot) ? g_rowmap[r] : 0;
        rowsS[tid] = tb;
        atomicMax(&needf[(tb & 255) >> 6], (tb >> 8) + 1);
    }
    __syncthreads();
    if (tid == 0) {
        #pragma unroll
        for (int g = 0; g < NBG; g++) {
            int need = needf[g];
            while (atomicAdd(&g_barflag2[g], 0) < need) { __nanosleep(128); }
        }
        __threadfence();
    }
    __syncthreads();

    int wp = tid >> 5, wm = wp & 1, wn = wp >> 1;   // warp tile 32 rows x 64 cols
    int srowA = tid >> 1, scA = (tid & 1) * 32;
    const bf16* arow = g_hall_bf + (size_t)rowsS[srowA] * HH + scA;
    int nb = n0 + tid;
    const bf16* brow = g_Wout_bf + (size_t)(nb < VV ? nb : VV - 1) * HH;
    bf16* asd = As + srowA * LDAB + scA;
    bf16* bsd = Bs + tid * LDAB;
    FragC c[2][4];
    FRAG_INIT(c);

    // prologue: chunks 0, 1
    #pragma unroll
    for (int s = 0; s < 2; s++) {
        const bf16* ags = arow + s * BKB;
        const bf16* bgs = brow + s * BKB;
        #pragma unroll
        for (int q = 0; q < 32; q += 8) cp16(asd + s * ACH2 + q, ags + q);
        #pragma unroll
        for (int q = 0; q < 64; q += 8) cp16(bsd + s * BCHO + q, bgs + q);
        asm volatile("cp.async.commit_group;");
    }
    #pragma unroll 1
    for (int ch = 0; ch < NCHUNK; ch++) {
        if (ch < NCHUNK - 1) asm volatile("cp.async.wait_group 1;" ::: "memory");
        else                 asm volatile("cp.async.wait_group 0;" ::: "memory");
        __syncthreads();
        if (ch < NCHUNK - 2) {
            int dch = ch + 2;
            int dbuf = dch; while (dbuf >= 3) dbuf -= 3;
            const bf16* ags = arow + dch * BKB;
            const bf16* bgs = brow + dch * BKB;
            #pragma unroll
            for (int q = 0; q < 32; q += 8) cp16(asd + dbuf * ACH2 + q, ags + q);
            #pragma unroll
            for (int q = 0; q < 64; q += 8) cp16(bsd + dbuf * BCHO + q, bgs + q);
            asm volatile("cp.async.commit_group;");
        }
        int cbuf = ch; while (cbuf >= 3) cbuf -= 3;
        bf16* Ab = As + cbuf * ACH2;
        bf16* Bb = Bs + cbuf * BCHO;
        #pragma unroll
        for (int kk = 0; kk < BKB; kk += 16) {
            FragA a0, a1; FragB bf[4];
            wmma::load_matrix_sync(a0, &Ab[(wm * 32)      * LDAB + kk], LDAB);
            wmma::load_matrix_sync(a1, &Ab[(wm * 32 + 16) * LDAB + kk], LDAB);
            #pragma unroll
            for (int j = 0; j < 4; j++)
                wmma::load_matrix_sync(bf[j], &Bb[(wn * 64 + j * 16) * LDAB + kk], LDAB);
            #pragma unroll
            for (int j = 0; j < 4; j++) {
                wmma::mma_sync(c[0][j], a0, bf[j], c[0][j]);
                wmma::mma_sync(c[1][j], a1, bf[j], c[1][j]);
            }
        }
    }
    __syncthreads();
    #pragma unroll
    for (int i = 0; i < 2; i++)
        #pragma unroll
        for (int j = 0; j < 4; j++)
            wmma::store_matrix_sync(&Cs[(wm * 32 + i * 16) * LDC + wn * 64 + j * 16],
                                    c[i][j], LDC, wmma::mem_row_major);
    __syncthreads();

    int row = tid >> 1, cb = (tid & 1) * 64;
    int r = m0 + row;
    if (r < ntot) {
        int tb2 = rowsS[row];
        int t = tb2 >> 8, b = tb2 & 255;
        size_t obase = ((size_t)b * ML + t) * VV;
        float psum = 0.f;
        #pragma unroll
        for (int q = 0; q < 16; q++) {
            int n = n0 + cb + q * 4;
            if (n < VV) {
                float4 cv = *(const float4*)&Cs[row * LDC + cb + q * 4];
                float4 bo = *(const float4*)(bout + n);
                float4 v;
                v.x = cv.x + bo.x; v.y = cv.y + bo.y;
                v.z = cv.z + bo.z; v.w = cv.w + bo.w;
                *(float4*)(out + obase + n) = v;
                psum += __expf(v.x) + __expf(v.y) + __expf(v.z) + __expf(v.w);
            }
        }
        atomicAdd(&g_rowsum[tb2], psum);
    }
}

// ---- final: full-output pass; zeros inactive/pad, log-softmax for active ----
__global__ __launch_bounds__(256) void k_out2(float* __restrict__ out) {
    long long idx = (long long)blockIdx.x * 256 + threadIdx.x;
    const int perRow = VV / 4;
    const long long TOT = (long long)BB * ML * perRow;
    if (idx >= TOT) return;
    int r = (int)(idx / perRow);
    int v4 = (int)(idx % perRow);
    int b = r / ML, t = r - b * ML;
    size_t p = (size_t)r * VV + v4 * 4;
    bool active = (t < TT) && (b < g_cnt[t]);
    float4 o = make_float4(0.f, 0.f, 0.f, 0.f);
    if (active) {
        float ls = logf(g_rowsum[t * BB + b]);
        float4 lv = *(const float4*)(out + p);
        o.x = lv.x - ls; o.y = lv.y - ls; o.z = lv.z - ls; o.w = lv.w - ls;
    }
    *(float4*)(out + p) = o;
}

// ---------------- launch ----------------
extern "C" void kernel_launch(void* const* d_in, const int* in_sizes, int n_in,
                              void* d_out, int out_size) {
    const float* gimg = (const float*)d_in[0];
    const int*   w    = (const int*)d_in[1];
    const int*   cap  = (const int*)d_in[2];
    const float* emb  = (const float*)d_in[3];
    const float* Wih  = (const float*)d_in[4];
    const float* Whh  = (const float*)d_in[5];
    const float* bih  = (const float*)d_in[6];
    const float* bhh  = (const float*)d_in[7];
    const float* Wout = (const float*)d_in[8];
    const float* bout = (const float*)d_in[9];
    float* out = (float*)d_out;

    static int attr_done = 0;
    if (!attr_done) {
        cudaFuncSetAttribute(k_proj,  cudaFuncAttributeMaxDynamicSharedMemorySize, DSMEM_BYTES);
        cudaFuncSetAttribute(k_fused, cudaFuncAttributeMaxDynamicSharedMemorySize, DSMEM_FUSED);
        attr_done = 1;
    }

    k_cvt<<<(int)((N_CVT2 + 255) / 256), 256>>>(Wih, Whh, Wout, emb, gimg);
    k_prep<<<1, 256>>>(w, cap, out, (long long)out_size);
    k_proj<<<dim3(16, 62), 256, DSMEM_BYTES>>>(w, bih, bhh);
    k_fused<<<NSTEPBLK + MT_MAX * NT_OUT1, 128, DSMEM_FUSED>>>(bout, out);
    long long tot = (long long)BB * ML * (VV / 4);
    k_out2<<<(int)((tot + 255) / 256), 256>>>(out);
}